// round 1
// baseline (speedup 1.0000x reference)
#include <cuda_runtime.h>

// ---------------------------------------------------------------------------
// VectorQuantize: fused pre-quantize + distance argmin + EMA update.
//
// Outputs concatenated (float32), reference return order:
//   quantize      (32,16,64,64) -> 2097152
//   ind_r         (32,16,64)    ->   32768  (indices cast to float)
//   loss          ()            ->       1
//   new_cluster   (8192,)       ->    8192
//   new_embed_avg (64,8192)     ->  524288
//   new_embed     (64,8192)     ->  524288
// ---------------------------------------------------------------------------

#define NROWS   32768
#define DIMK    64
#define NCODES  8192
#define RPB     128            // rows per block
#define CTILE   128            // codes per tile
#define NTILES  (NCODES / CTILE)

#define OFF_Q     0
#define OFF_IND   2097152
#define OFF_LOSS  2129920
#define OFF_NC    2129921
#define OFF_EA    2138113
#define OFF_NE    2662401
#define OUT_FULL  3186689

// scratch (device globals: no allocations allowed)
__device__ float g_pe[16 * 64 * 64];        // effective PE per (c,i) row, 64 wide
__device__ float g_cn[NCODES];              // -0.5 * ||e_j||^2
__device__ float g_counts[NCODES];
__device__ float g_esum[DIMK * NCODES];     // embed_sum, (64, 8192)
__device__ float g_loss;
__device__ float g_total;

// ---- packed f32x2 helpers (sm_103a) ----
__device__ __forceinline__ unsigned long long pk2(float a, float b) {
    unsigned long long r;
    asm("mov.b64 %0, {%1, %2};" : "=l"(r) : "f"(a), "f"(b));
    return r;
}
__device__ __forceinline__ void fma2(unsigned long long& d, unsigned long long a,
                                     unsigned long long b) {
    asm("fma.rn.f32x2 %0, %1, %2, %0;" : "+l"(d) : "l"(a), "l"(b));
}
__device__ __forceinline__ void upk(unsigned long long v, float& lo, float& hi) {
    asm("mov.b64 {%0, %1}, %2;" : "=f"(lo), "=f"(hi) : "l"(v));
}

// ---------------------------------------------------------------------------
// prep: build effective PE table, code half-norms, zero scratch
// grid 256 x 256  (65536 threads)
// ---------------------------------------------------------------------------
__global__ void vq_prep(const float* __restrict__ pos_emb,
                        const float* __restrict__ embed) {
    int idx = blockIdx.x * 256 + threadIdx.x;  // 0..65535
    int j = idx & 63;
    int i = (idx >> 6) & 63;
    int c = idx >> 12;
    int s = ((i >> 2) << 4) + (j >> 2);
    int d = (c << 4) + ((i & 3) << 2) + (j & 3);
    g_pe[idx] = pos_emb[s * 256 + d];

#pragma unroll
    for (int t = 0; t < 8; t++) g_esum[idx + t * 65536] = 0.0f;

    if (idx < NCODES) {
        g_counts[idx] = 0.0f;
        float s2 = 0.0f;
#pragma unroll
        for (int k = 0; k < DIMK; k++) {
            float v = embed[k * NCODES + idx];
            s2 += v * v;
        }
        g_cn[idx] = -0.5f * s2;
    }
    if (idx == 0) { g_loss = 0.0f; g_total = 0.0f; }
}

// ---------------------------------------------------------------------------
// main: fused dist GEMM + argmin + gather/scatter epilogue
// 256 blocks x 256 threads, 2 blocks/SM
// ---------------------------------------------------------------------------
__global__ void __launch_bounds__(256, 2)
vq_main(const float* __restrict__ input, const float* __restrict__ embed,
        float* __restrict__ out, int full) {
    extern __shared__ float smem[];
    float* Xs  = smem;                 // [64][128]  x = input + pe, transposed
    float* Es  = smem + 64 * 128;      // [64][128]  code tile (also reduce buf)
    float* CNs = smem + 2 * 64 * 128;  // [128]
    int*   IndSh  = (int*)(CNs + 128); // [128]
    float* LossSh = (float*)(IndSh + 128);

    const int tid = threadIdx.x;
    const int tx = tid & 15;
    const int ty = tid >> 4;
    const int row0 = blockIdx.x * RPB;

    // ---- load X tile (add PE), store transposed [k][row] ----
    {
        int r = tid >> 1;
        int half = tid & 1;
        int rg = row0 + r;
        const float4* ip = (const float4*)(input + (size_t)rg * 64 + half * 32);
        const float4* pp = (const float4*)(g_pe + (size_t)(rg & 1023) * 64 + half * 32);
#pragma unroll
        for (int q = 0; q < 8; q++) {
            float4 a = ip[q];
            float4 b = pp[q];
            int kb = half * 32 + q * 4;
            Xs[(kb + 0) * RPB + r] = a.x + b.x;
            Xs[(kb + 1) * RPB + r] = a.y + b.y;
            Xs[(kb + 2) * RPB + r] = a.z + b.z;
            Xs[(kb + 3) * RPB + r] = a.w + b.w;
        }
        if (tid == 0) LossSh[0] = 0.0f;
    }

    float best[8];
    int   bidx[8];
#pragma unroll
    for (int rr = 0; rr < 8; rr++) { best[rr] = -3.4e38f; bidx[rr] = 0; }

    for (int t = 0; t < NTILES; t++) {
        const int cb = t * CTILE;
        __syncthreads();  // everyone done reading previous Es (and Xs ready)
        // ---- load E tile + CN tile ----
#pragma unroll
        for (int i2 = 0; i2 < 8; i2++) {
            int idx = tid + 256 * i2;          // 0..2047 float4s
            int kr = idx >> 5;
            int c4 = idx & 31;
            float4 v = *(const float4*)(embed + (size_t)kr * NCODES + cb + c4 * 4);
            *(float4*)(Es + kr * CTILE + c4 * 4) = v;
        }
        if (tid < 32) {
            float4 v = *(const float4*)(g_cn + cb + tid * 4);
            *(float4*)(CNs + tid * 4) = v;
        }
        __syncthreads();

        // ---- register-tiled score: 8 rows x 4 code-pairs per thread ----
        unsigned long long acc[8][4];
        {
            const unsigned long long* cnp = (const unsigned long long*)CNs;
            unsigned long long c0 = cnp[tx], c1 = cnp[tx + 16];
            unsigned long long c2 = cnp[tx + 32], c3 = cnp[tx + 48];
#pragma unroll
            for (int rr = 0; rr < 8; rr++) {
                acc[rr][0] = c0; acc[rr][1] = c1; acc[rr][2] = c2; acc[rr][3] = c3;
            }
        }
#pragma unroll 8
        for (int k = 0; k < 64; k++) {
            const unsigned long long* ep = (const unsigned long long*)(Es + k * CTILE);
            unsigned long long e0 = ep[tx], e1 = ep[tx + 16];
            unsigned long long e2 = ep[tx + 32], e3 = ep[tx + 48];
#pragma unroll
            for (int rr = 0; rr < 8; rr++) {
                float xv = Xs[k * RPB + ty + 16 * rr];
                unsigned long long x2 = pk2(xv, xv);
                fma2(acc[rr][0], x2, e0);
                fma2(acc[rr][1], x2, e1);
                fma2(acc[rr][2], x2, e2);
                fma2(acc[rr][3], x2, e3);
            }
        }
        // ---- per-thread running argmax (in-thread scan is ascending j) ----
#pragma unroll
        for (int rr = 0; rr < 8; rr++) {
#pragma unroll
            for (int cp = 0; cp < 4; cp++) {
                float lo, hi;
                upk(acc[rr][cp], lo, hi);
                int j0 = cb + 2 * (tx + 16 * cp);
                if (lo > best[rr]) { best[rr] = lo; bidx[rr] = j0; }
                if (hi > best[rr]) { best[rr] = hi; bidx[rr] = j0 + 1; }
            }
        }
    }

    // ---- cross-thread argmax reduce (16 tx threads share each row) ----
    __syncthreads();
    float2* red = (float2*)Es;  // [128][16]
#pragma unroll
    for (int rr = 0; rr < 8; rr++) {
        int rloc = ty + 16 * rr;
        float2 e;
        e.x = best[rr];
        e.y = __int_as_float(bidx[rr]);
        red[rloc * 16 + tx] = e;
    }
    __syncthreads();
    if (tid < 128) {
        int rloc = tid;
        float bv = -3.4e38f;
        int bj = 0x7fffffff;
#pragma unroll
        for (int q = 0; q < 16; q++) {
            float2 e = red[rloc * 16 + q];
            int j = __float_as_int(e.y);
            if (e.x > bv || (e.x == bv && j < bj)) { bv = e.x; bj = j; }
        }
        IndSh[rloc] = bj;
        int rg = row0 + rloc;
        if (full) out[OFF_IND + rg] = (float)bj;
        atomicAdd(&g_counts[bj], 1.0f);
    }
    __syncthreads();

    // ---- epilogue: gather codebook, quantize out, loss, embed_sum scatter ----
    const int wid = tid >> 5, lane = tid & 31;
    float lsum = 0.0f;
    for (int it = 0; it < 16; it++) {
        int rloc = wid * 16 + it;
        int rg = row0 + rloc;
        int j = IndSh[rloc];
#pragma unroll
        for (int h = 0; h < 2; h++) {
            int k = lane + 32 * h;
            float ev = embed[(size_t)k * NCODES + j];
            float iv = input[(size_t)rg * 64 + k];
            float dd = ev - iv;
            lsum += dd * dd;
            out[OFF_Q + (size_t)rg * 64 + k] = ev;
            atomicAdd(&g_esum[(size_t)k * NCODES + j], Xs[k * RPB + rloc]);
        }
    }
#pragma unroll
    for (int off = 16; off; off >>= 1)
        lsum += __shfl_down_sync(0xffffffffu, lsum, off);
    if (lane == 0) atomicAdd(LossSh, lsum);
    __syncthreads();
    if (tid == 0) atomicAdd(&g_loss, LossSh[0]);
}

// ---------------------------------------------------------------------------
// finalize 1: new_cluster + total   (32 x 256)
// ---------------------------------------------------------------------------
__global__ void vq_fin1(const float* __restrict__ cs, float* __restrict__ out) {
    int j = blockIdx.x * 256 + threadIdx.x;
    float nc = 0.8f * cs[j] + 0.2f * g_counts[j];
    out[OFF_NC + j] = nc;
    __shared__ float sh[256];
    sh[threadIdx.x] = nc;
    __syncthreads();
    for (int s = 128; s; s >>= 1) {
        if (threadIdx.x < s) sh[threadIdx.x] += sh[threadIdx.x + s];
        __syncthreads();
    }
    if (threadIdx.x == 0) atomicAdd(&g_total, sh[0]);
}

// ---------------------------------------------------------------------------
// finalize 2: new_embed_avg, new_embed, loss   (2048 x 256)
// ---------------------------------------------------------------------------
__global__ void vq_fin2(const float* __restrict__ ea, float* __restrict__ out) {
    int idx = blockIdx.x * 256 + threadIdx.x;  // 0..524287
    int j = idx & (NCODES - 1);
    float nea = 0.8f * ea[idx] + 0.2f * g_esum[idx];
    out[OFF_EA + idx] = nea;
    float total = g_total;
    float nc = out[OFF_NC + j];
    float smoothed = (nc + 1e-5f) / (total + NCODES * 1e-5f) * total;
    out[OFF_NE + idx] = nea / smoothed;
    if (idx == 0) out[OFF_LOSS] = g_loss * (1.0f / 2097152.0f);
}

// ---------------------------------------------------------------------------
extern "C" void kernel_launch(void* const* d_in, const int* in_sizes, int n_in,
                              void* d_out, int out_size) {
    const float* input = (const float*)d_in[0];   // (32,16,64,64)
    const float* embed = (const float*)d_in[1];   // (64,8192)
    const float* pos   = (const float*)d_in[2];   // (2048,256)
    const float* cs    = (const float*)d_in[3];   // (8192,)
    const float* ea    = (const float*)d_in[4];   // (64,8192)
    float* out = (float*)d_out;

    const int smem_main = (64 * 128 + 64 * 128 + 128) * 4 + 128 * 4 + 64;
    cudaFuncSetAttribute(vq_main, cudaFuncAttributeMaxDynamicSharedMemorySize,
                         smem_main);

    int full = (out_size >= OUT_FULL) ? 1 : 0;

    vq_prep<<<256, 256>>>(pos, embed);
    vq_main<<<256, 256, smem_main>>>(input, embed, out, full);
    if (full) {
        vq_fin1<<<NCODES / 256, 256>>>(cs, out);
        vq_fin2<<<(DIMK * NCODES) / 256, 256>>>(ea, out);
    }
}

// round 3
// speedup vs baseline: 1.0344x; 1.0344x over previous
#include <cuda_runtime.h>
#include <cstdint>

// ---------------------------------------------------------------------------
// VectorQuantize via mma.sync tf32 (3xTF32 emulated fp32) + exact rescore.
// Outputs (float32, concatenated): quantize, ind_r, loss, new_cluster,
// new_embed_avg, new_embed.
// ---------------------------------------------------------------------------

#define NCODES 8192
#define OFF_Q     0
#define OFF_IND   2097152
#define OFF_LOSS  2129920
#define OFF_NC    2129921
#define OFF_EA    2138113
#define OFF_NE    2662401
#define OUT_FULL  3186689

#define RPB    128
#define NTILES 64

// smem word offsets (floats)
#define W_XH   0        // [16 q][128 row][4 kline]  = 8192 words
#define W_XL   8192
#define W_B    16384    // 2 bufs x (BH 8192 + BL 8192) = 32768 words
#define W_CN   49152    // 2 x 128
#define W_IND  49408    // 128 ints
#define W_RED  49536    // 2 halves x 128 float2 = 512 words
#define W_LOSS 50048
#define SMEM_TOTAL 200704   // bytes

// device scratch
__device__ float g_pe[65536];
__device__ float g_cn[NCODES];
__device__ float g_counts[NCODES];
__device__ float g_esum[64 * NCODES];
__device__ float g_eh[NCODES * 64];   // E^T tf32-hi, [j][k]
__device__ float g_el[NCODES * 64];   // E^T tf32-lo, [j][k]
__device__ float g_loss, g_total;

// ---------------------------------------------------------------------------
__device__ __forceinline__ uint32_t smem_u32(const void* p) {
    uint32_t a;
    asm("{ .reg .u64 t; cvta.to.shared.u64 t, %1; cvt.u32.u64 %0, t; }"
        : "=r"(a) : "l"(p));
    return a;
}
__device__ __forceinline__ float tf32r(float x) {
    float r;
    asm("cvt.rna.tf32.f32 %0, %1;" : "=f"(r) : "f"(x));
    return r;
}
__device__ __forceinline__ void mma8(float* d, uint32_t a0, uint32_t a1,
                                     uint32_t a2, uint32_t a3,
                                     uint32_t b0, uint32_t b1) {
    asm volatile(
        "mma.sync.aligned.m16n8k8.row.col.f32.tf32.tf32.f32 "
        "{%0,%1,%2,%3}, {%4,%5,%6,%7}, {%8,%9}, {%0,%1,%2,%3};"
        : "+f"(d[0]), "+f"(d[1]), "+f"(d[2]), "+f"(d[3])
        : "r"(a0), "r"(a1), "r"(a2), "r"(a3), "r"(b0), "r"(b1));
}
__device__ __forceinline__ void cp16(uint32_t dst, const void* src) {
    asm volatile("cp.async.cg.shared.global [%0], [%1], 16;"
                 :: "r"(dst), "l"(src) : "memory");
}
#define CP_COMMIT() asm volatile("cp.async.commit_group;" ::: "memory")
#define CP_WAIT1()  asm volatile("cp.async.wait_group 1;" ::: "memory")

// ---------------------------------------------------------------------------
// prep: PE table, code norms, E^T tf32 hi/lo, zero scratch.  grid 2048 x 256
// ---------------------------------------------------------------------------
__global__ void vq_prep(const float* __restrict__ pos_emb,
                        const float* __restrict__ embed) {
    int idx = blockIdx.x * 256 + threadIdx.x;   // 0..524287
    int k = idx >> 13, j = idx & 8191;
    float v = embed[(size_t)k * NCODES + j];
    float vh = tf32r(v);
    g_eh[(size_t)j * 64 + k] = vh;
    g_el[(size_t)j * 64 + k] = tf32r(v - vh);
    g_esum[idx] = 0.0f;
    if (idx < 65536) {
        int jj = idx & 63, i = (idx >> 6) & 63, c = idx >> 12;
        int s = ((i >> 2) << 4) + (jj >> 2);
        int d = (c << 4) + ((i & 3) << 2) + (jj & 3);
        g_pe[idx] = pos_emb[s * 256 + d];
    }
    if (idx < NCODES) {
        g_counts[idx] = 0.0f;
        float s2 = 0.0f;
#pragma unroll
        for (int kk = 0; kk < 64; kk++) {
            float e = embed[kk * NCODES + idx];
            s2 += e * e;
        }
        g_cn[idx] = -0.5f * s2;
    }
    if (idx == 0) { g_loss = 0.0f; g_total = 0.0f; }
}

// ---------------------------------------------------------------------------
// async B tile load: g_eh/g_el [j][k] -> smem [q][col][kline] (layout-
// preserving per 16B chunk), plus cn tile. 4128 x 16B per tile.
// ---------------------------------------------------------------------------
__device__ __forceinline__ void load_b_tile(uint32_t smem_base, int t, int tid) {
    const int cb = t * 128;
    uint32_t bb = smem_base + (uint32_t)(W_B + (t & 1) * 16384) * 4u;
#pragma unroll
    for (int i = 0; i < 16; i++) {
        int id = tid + (i << 8);            // 0..4095
        int arr = id >> 11;                 // 0 hi, 1 lo
        int rem = id & 2047;
        int j = rem >> 4, q = rem & 15;
        const float* src = (arr ? g_el : g_eh) + (size_t)(cb + j) * 64 + q * 4;
        uint32_t dst = bb + (uint32_t)(arr * 8192 + (q << 9) + (j << 2)) * 4u;
        cp16(dst, src);
    }
    if (tid < 32)
        cp16(smem_base + (uint32_t)(W_CN + (t & 1) * 128 + tid * 4) * 4u,
             g_cn + cb + tid * 4);
}

// ---------------------------------------------------------------------------
// main: 256 CTAs x 256 threads. warp tile 32 rows x 64 cols, 3xTF32 mma.
// ---------------------------------------------------------------------------
__global__ void __launch_bounds__(256, 1)
vq_main(const float* __restrict__ input, const float* __restrict__ embed,
        float* __restrict__ out, int full) {
    extern __shared__ float smf[];
    const uint32_t smem_base = smem_u32(smf);
    const int tid = threadIdx.x, wid = tid >> 5, lane = tid & 31;
    const int wr = wid >> 1, wc = wid & 1;
    const int g = lane >> 2, kl = lane & 3;
    const int row0 = blockIdx.x * RPB;

    int* IndSh = (int*)(smf + W_IND);
    float2* RED = (float2*)(smf + W_RED);

    if (tid == 0) smf[W_LOSS] = 0.0f;

    // ---- build X hi/lo in smem ----
    {
        int row = tid >> 1, h = tid & 1;
        int rg = row0 + row;
        const float4* ip = (const float4*)(input + (size_t)rg * 64);
        const float4* pp = (const float4*)(g_pe + (size_t)(rg & 1023) * 64);
#pragma unroll
        for (int i = 0; i < 8; i++) {
            int q = h * 8 + i;
            float4 a = ip[q], b = pp[q];
            float x0 = a.x + b.x, x1 = a.y + b.y;
            float x2 = a.z + b.z, x3 = a.w + b.w;
            float4 hh, ll;
            hh.x = tf32r(x0); ll.x = tf32r(x0 - hh.x);
            hh.y = tf32r(x1); ll.y = tf32r(x1 - hh.y);
            hh.z = tf32r(x2); ll.z = tf32r(x2 - hh.z);
            hh.w = tf32r(x3); ll.w = tf32r(x3 - hh.w);
            *(float4*)(smf + W_XH + q * 512 + row * 4) = hh;
            *(float4*)(smf + W_XL + q * 512 + row * 4) = ll;
        }
    }
    load_b_tile(smem_base, 0, tid); CP_COMMIT();
    load_b_tile(smem_base, 1, tid); CP_COMMIT();

    float best[4];
    int bcol[4];
#pragma unroll
    for (int s = 0; s < 4; s++) { best[s] = -3.4e38f; bcol[s] = 0; }

    const uint32_t* XHu = (const uint32_t*)(smf + W_XH);
    const uint32_t* XLu = (const uint32_t*)(smf + W_XL);
    const int rbase = wr * 32 + g;

    for (int t = 0; t < NTILES; t++) {
        CP_WAIT1();
        __syncthreads();
        const uint32_t* BH = (const uint32_t*)(smf + W_B + (t & 1) * 16384);
        const uint32_t* BL = BH + 8192;
        const float* cn = smf + W_CN + (t & 1) * 128 + wc * 64;

        float acc[2][8][4];
#pragma unroll
        for (int nf = 0; nf < 8; nf++) {
            float c0 = cn[nf * 8 + 2 * kl];
            float c1 = cn[nf * 8 + 2 * kl + 1];
#pragma unroll
            for (int r2 = 0; r2 < 2; r2++) {
                acc[r2][nf][0] = c0; acc[r2][nf][1] = c1;
                acc[r2][nf][2] = c0; acc[r2][nf][3] = c1;
            }
        }
#pragma unroll
        for (int kc = 0; kc < 8; kc++) {
            uint32_t ah[4][2], al[4][2];
#pragma unroll
            for (int h = 0; h < 2; h++) {
                int qw = (2 * kc + h) * 512 + kl;
#pragma unroll
                for (int s = 0; s < 4; s++) {
                    ah[s][h] = XHu[qw + (rbase + 8 * s) * 4];
                    al[s][h] = XLu[qw + (rbase + 8 * s) * 4];
                }
            }
#pragma unroll
            for (int nf = 0; nf < 8; nf++) {
                int colw = (2 * kc) * 512 + (wc * 64 + nf * 8 + g) * 4 + kl;
                uint32_t bh0 = BH[colw], bh1 = BH[colw + 512];
                uint32_t bl0 = BL[colw], bl1 = BL[colw + 512];
                mma8(acc[0][nf], ah[0][0], ah[1][0], ah[0][1], ah[1][1], bh0, bh1);
                mma8(acc[0][nf], ah[0][0], ah[1][0], ah[0][1], ah[1][1], bl0, bl1);
                mma8(acc[0][nf], al[0][0], al[1][0], al[0][1], al[1][1], bh0, bh1);
                mma8(acc[1][nf], ah[2][0], ah[3][0], ah[2][1], ah[3][1], bh0, bh1);
                mma8(acc[1][nf], ah[2][0], ah[3][0], ah[2][1], ah[3][1], bl0, bl1);
                mma8(acc[1][nf], al[2][0], al[3][0], al[2][1], al[3][1], bh0, bh1);
            }
        }
        // extraction: running per-slot argmax (cols ascend => strict > keeps
        // the lowest index on ties)
        int colbase0 = t * 128 + wc * 64 + 2 * kl;
#pragma unroll
        for (int r2 = 0; r2 < 2; r2++) {
#pragma unroll
            for (int nf = 0; nf < 8; nf++) {
                int c01 = colbase0 + nf * 8;
                float v0 = acc[r2][nf][0], v1 = acc[r2][nf][1];
                float v2 = acc[r2][nf][2], v3 = acc[r2][nf][3];
                int s0 = 2 * r2, s1 = 2 * r2 + 1;
                if (v0 > best[s0]) { best[s0] = v0; bcol[s0] = c01; }
                if (v1 > best[s0]) { best[s0] = v1; bcol[s0] = c01 + 1; }
                if (v2 > best[s1]) { best[s1] = v2; bcol[s1] = c01; }
                if (v3 > best[s1]) { best[s1] = v3; bcol[s1] = c01 + 1; }
            }
        }
        __syncthreads();
        if (t + 2 < NTILES) load_b_tile(smem_base, t + 2, tid);
        CP_COMMIT();
    }

    // ---- quad reduce (4 lanes per row within a warp-half) ----
#pragma unroll
    for (int s = 0; s < 4; s++) {
        float v = best[s];
        int c = bcol[s];
#pragma unroll
        for (int off = 1; off <= 2; off <<= 1) {
            float ov = __shfl_xor_sync(0xffffffffu, v, off);
            int oc = __shfl_xor_sync(0xffffffffu, c, off);
            if (ov > v || (ov == v && oc < c)) { v = ov; c = oc; }
        }
        if ((lane & 3) == 0)
            RED[wc * 128 + wr * 32 + g + 8 * s] = make_float2(v, __int_as_float(c));
    }
    __syncthreads();

    // ---- exact fp32 rescore of the two half-winners per row ----
    if (tid < 128) {
        int row = tid, rg = row0 + row;
        float xv[64];
        const float4* ip = (const float4*)(input + (size_t)rg * 64);
        const float4* pp = (const float4*)(g_pe + (size_t)(rg & 1023) * 64);
#pragma unroll
        for (int q = 0; q < 16; q++) {
            float4 a = ip[q], b = pp[q];
            xv[q * 4 + 0] = a.x + b.x; xv[q * 4 + 1] = a.y + b.y;
            xv[q * 4 + 2] = a.z + b.z; xv[q * 4 + 3] = a.w + b.w;
        }
        int c0 = __float_as_int(RED[row].y);
        int c1 = __float_as_int(RED[128 + row].y);
        float s0 = g_cn[c0], s1 = g_cn[c1];
#pragma unroll 16
        for (int k = 0; k < 64; k++) {
            s0 = fmaf(xv[k], embed[(size_t)k * NCODES + c0], s0);
            s1 = fmaf(xv[k], embed[(size_t)k * NCODES + c1], s1);
        }
        int bj = (s1 > s0 || (s1 == s0 && c1 < c0)) ? c1 : c0;
        IndSh[row] = bj;
        if (full) out[OFF_IND + rg] = (float)bj;
        atomicAdd(&g_counts[bj], 1.0f);
    }
    __syncthreads();

    // ---- epilogue: quantize gather, loss, embed_sum scatter ----
    {
        float lsum = 0.0f;
        for (int it = 0; it < 16; it++) {
            int rloc = wid * 16 + it;
            int rg = row0 + rloc;
            int j = IndSh[rloc];
#pragma unroll
            for (int h2 = 0; h2 < 2; h2++) {
                int k = lane + 32 * h2;
                float ev = embed[(size_t)k * NCODES + j];
                float iv = input[(size_t)rg * 64 + k];
                float dd = ev - iv;
                lsum += dd * dd;
                out[OFF_Q + (size_t)rg * 64 + k] = ev;
                float xv2 = iv + g_pe[(rg & 1023) * 64 + k];
                atomicAdd(&g_esum[(size_t)k * NCODES + j], xv2);
            }
        }
#pragma unroll
        for (int off = 16; off; off >>= 1)
            lsum += __shfl_down_sync(0xffffffffu, lsum, off);
        if (lane == 0) atomicAdd(smf + W_LOSS, lsum);
    }
    __syncthreads();
    if (tid == 0) atomicAdd(&g_loss, smf[W_LOSS]);
}

// ---------------------------------------------------------------------------
__global__ void vq_fin1(const float* __restrict__ cs, float* __restrict__ out) {
    int j = blockIdx.x * 256 + threadIdx.x;
    float nc = 0.8f * cs[j] + 0.2f * g_counts[j];
    out[OFF_NC + j] = nc;
    __shared__ float sh[256];
    sh[threadIdx.x] = nc;
    __syncthreads();
    for (int s = 128; s; s >>= 1) {
        if (threadIdx.x < s) sh[threadIdx.x] += sh[threadIdx.x + s];
        __syncthreads();
    }
    if (threadIdx.x == 0) atomicAdd(&g_total, sh[0]);
}

__global__ void vq_fin2(const float* __restrict__ ea, float* __restrict__ out) {
    int idx = blockIdx.x * 256 + threadIdx.x;
    int j = idx & (NCODES - 1);
    float nea = 0.8f * ea[idx] + 0.2f * g_esum[idx];
    out[OFF_EA + idx] = nea;
    float total = g_total;
    float nc = out[OFF_NC + j];
    float smoothed = (nc + 1e-5f) / (total + NCODES * 1e-5f) * total;
    out[OFF_NE + idx] = nea / smoothed;
    if (idx == 0) out[OFF_LOSS] = g_loss * (1.0f / 2097152.0f);
}

// ---------------------------------------------------------------------------
extern "C" void kernel_launch(void* const* d_in, const int* in_sizes, int n_in,
                              void* d_out, int out_size) {
    const float* input = (const float*)d_in[0];
    const float* embed = (const float*)d_in[1];
    const float* pos   = (const float*)d_in[2];
    const float* cs    = (const float*)d_in[3];
    const float* ea    = (const float*)d_in[4];
    float* out = (float*)d_out;

    cudaFuncSetAttribute(vq_main, cudaFuncAttributeMaxDynamicSharedMemorySize,
                         SMEM_TOTAL);
    int full = (out_size >= OUT_FULL) ? 1 : 0;

    vq_prep<<<2048, 256>>>(pos, embed);
    vq_main<<<256, 256, SMEM_TOTAL>>>(input, embed, out, full);
    if (full) {
        vq_fin1<<<NCODES / 256, 256>>>(cs, out);
        vq_fin2<<<(64 * NCODES) / 256, 256>>>(ea, out);
    }
}

// round 4
// speedup vs baseline: 2.3798x; 2.3007x over previous
#include <cuda_runtime.h>
#include <cuda_fp16.h>
#include <cstdint>

// ---------------------------------------------------------------------------
// VectorQuantize via mma.sync.m16n8k16.f16 (3xFP16 emulated fp32) + exact
// fp32 rescore. Outputs: quantize, ind_r, loss, new_cluster, new_embed_avg,
// new_embed (float32, concatenated).
// ---------------------------------------------------------------------------

#define NCODES 8192
#define OFF_Q     0
#define OFF_IND   2097152
#define OFF_LOSS  2129920
#define OFF_NC    2129921
#define OFF_EA    2138113
#define OFF_NE    2662401
#define OUT_FULL  3186689

#define RPB    128
#define NTILES 64

// smem word offsets
#define W_AH   0        // [4 kc16][128 row][8 w] fp16x2 words
#define W_AL   4096
#define W_B    8192     // 2 bufs x (hi 4096 + lo 4096)
#define W_CN   24576    // 2 x 128
#define W_IND  24832
#define W_RED  24960    // 2 halves x 128 float2
#define W_LOSS 25472
#define SMEM_TOTAL 101920

// device scratch
__device__ float g_pe[65536];
__device__ __align__(16) float g_cn[NCODES];
__device__ float g_counts[NCODES];
__device__ float g_esum[64 * NCODES];
__device__ __align__(16) float g_et[NCODES * 64];       // E^T fp32 [j][k]
__device__ __align__(16) uint32_t g_eh16[NCODES * 32];  // E^T fp16x2 hi [j][k/2]
__device__ __align__(16) uint32_t g_el16[NCODES * 32];  // E^T fp16x2 lo
__device__ float g_loss, g_total;

// ---------------------------------------------------------------------------
__device__ __forceinline__ uint32_t smem_u32(const void* p) {
    uint32_t a;
    asm("{ .reg .u64 t; cvta.to.shared.u64 t, %1; cvt.u32.u64 %0, t; }"
        : "=r"(a) : "l"(p));
    return a;
}
__device__ __forceinline__ void mma16(float* d, const uint32_t* a,
                                      uint32_t b0, uint32_t b1) {
    asm volatile(
        "mma.sync.aligned.m16n8k16.row.col.f32.f16.f16.f32 "
        "{%0,%1,%2,%3}, {%4,%5,%6,%7}, {%8,%9}, {%0,%1,%2,%3};"
        : "+f"(d[0]), "+f"(d[1]), "+f"(d[2]), "+f"(d[3])
        : "r"(a[0]), "r"(a[1]), "r"(a[2]), "r"(a[3]), "r"(b0), "r"(b1));
}
__device__ __forceinline__ void cp16(uint32_t dst, const void* src) {
    asm volatile("cp.async.cg.shared.global [%0], [%1], 16;"
                 :: "r"(dst), "l"(src) : "memory");
}
#define CP_COMMIT() asm volatile("cp.async.commit_group;" ::: "memory")
#define CP_WAIT1()  asm volatile("cp.async.wait_group 1;" ::: "memory")

__device__ __forceinline__ uint32_t pkh(float a, float b) {
    __half2 h = __floats2half2_rn(a, b);
    return *(uint32_t*)&h;
}

// ---------------------------------------------------------------------------
// prep0: PE table, zero scratch.  grid 2048 x 256
// ---------------------------------------------------------------------------
__global__ void vq_prep0(const float* __restrict__ pos_emb) {
    int idx = blockIdx.x * 256 + threadIdx.x;   // 0..524287
    g_esum[idx] = 0.0f;
    if (idx < 65536) {
        int jj = idx & 63, i = (idx >> 6) & 63, c = idx >> 12;
        int s = ((i >> 2) << 4) + (jj >> 2);
        int d = (c << 4) + ((i & 3) << 2) + (jj & 3);
        g_pe[idx] = pos_emb[s * 256 + d];
    }
    if (idx < NCODES) g_counts[idx] = 0.0f;
    if (idx == 0) { g_loss = 0.0f; g_total = 0.0f; }
}

// ---------------------------------------------------------------------------
// prep1: transpose embed -> g_et, fp16 hi/lo splits, code norms.
// grid 64 x 256, block handles 128 codes.
// ---------------------------------------------------------------------------
__global__ void vq_prep1(const float* __restrict__ embed) {
    __shared__ float sE[64][129];
    __shared__ float scn[128][2];
    const int tid = threadIdx.x;
    const int j0 = blockIdx.x * 128;
#pragma unroll 4
    for (int kk = 0; kk < 32; kk++) {
        int k = kk * 2 + (tid >> 7);
        int jl = tid & 127;
        sE[k][jl] = embed[(size_t)k * NCODES + j0 + jl];
    }
    __syncthreads();
    const int jl = tid & 127, kh = tid >> 7;
    const int j = j0 + jl;
    float ssum = 0.0f;
#pragma unroll
    for (int kx = 0; kx < 16; kx++) {
        int k = kh * 32 + kx * 2;
        float v0 = sE[k][jl], v1 = sE[k + 1][jl];
        ssum += v0 * v0 + v1 * v1;
        *(float2*)(g_et + (size_t)j * 64 + k) = make_float2(v0, v1);
        __half h0 = __float2half_rn(v0), h1 = __float2half_rn(v1);
        float l0 = v0 - __half2float(h0), l1 = v1 - __half2float(h1);
        g_eh16[(size_t)j * 32 + (k >> 1)] = pkh(v0, v1) * 0 + pkh(__half2float(h0), __half2float(h1));
        g_el16[(size_t)j * 32 + (k >> 1)] = pkh(l0, l1);
    }
    scn[jl][kh] = ssum;
    __syncthreads();
    if (tid < 128) g_cn[j0 + tid] = -0.5f * (scn[tid][0] + scn[tid][1]);
}

// ---------------------------------------------------------------------------
// async B tile: g_eh16/g_el16 [j][k/2] -> smem [kc16][col][w] swizzled
// ---------------------------------------------------------------------------
__device__ __forceinline__ void load_b_tile(uint32_t smem_base, int t, int tid) {
    const int cb = t * 128;
    const uint32_t bb = smem_base + (uint32_t)(W_B + (t & 1) * 8192) * 4u;
#pragma unroll
    for (int i = 0; i < 8; i++) {
        int c = tid + (i << 8);             // 0..2047
        int arr = c >> 10;                  // 0 hi, 1 lo
        int rem = c & 1023;
        int j = rem >> 3, ch = rem & 7;     // ch: 16B chunk within 128B row
        int kc16 = ch >> 1, half8 = ch & 1;
        const uint32_t* src = (arr ? g_el16 : g_eh16) + (size_t)(cb + j) * 32 + ch * 4;
        uint32_t dstw = (uint32_t)(arr * 4096 + kc16 * 1024 + j * 8 +
                                   ((half8 ^ ((j >> 2) & 1)) << 2));
        cp16(bb + dstw * 4u, src);
    }
    if (tid < 32)
        cp16(smem_base + (uint32_t)(W_CN + (t & 1) * 128) * 4u + tid * 16,
             g_cn + cb + tid * 4);
}

// ---------------------------------------------------------------------------
// main: 256 CTAs x 256 threads, 2 CTAs/SM. warp tile 32x64, 3xFP16 mma.
// ---------------------------------------------------------------------------
__global__ void __launch_bounds__(256, 2)
vq_main(const float* __restrict__ input, float* __restrict__ out, int full) {
    extern __shared__ float smf[];
    const uint32_t smem_base = smem_u32(smf);
    const int tid = threadIdx.x, wid = tid >> 5, lane = tid & 31;
    const int wr = wid >> 1, wc = wid & 1;
    const int g = lane >> 2, kl = lane & 3;
    const int row0 = blockIdx.x * RPB;

    int* IndSh = (int*)(smf + W_IND);
    float2* RED = (float2*)(smf + W_RED);
    if (tid == 0) smf[W_LOSS] = 0.0f;

    // ---- A build: X = input + pe, fp16 hi/lo, fragment-native layout ----
    {
        int row = tid >> 1, h = tid & 1, rg = row0 + row;
        const float4* ip = (const float4*)(input + (size_t)rg * 64);
        const float4* pp = (const float4*)(g_pe + (size_t)(rg & 1023) * 64);
        int swz = ((row >> 2) & 1) << 2;
#pragma unroll
        for (int i = 0; i < 8; i++) {
            int q = h * 8 + i;
            int k0 = 4 * q, kc16 = k0 >> 4, o = k0 & 15, w = o >> 1;
            float4 a = ip[q], b = pp[q];
            float x0 = a.x + b.x, x1 = a.y + b.y;
            float x2 = a.z + b.z, x3 = a.w + b.w;
            __half h0 = __float2half_rn(x0), h1 = __float2half_rn(x1);
            __half h2 = __float2half_rn(x2), h3 = __float2half_rn(x3);
            float l0 = x0 - __half2float(h0), l1 = x1 - __half2float(h1);
            float l2 = x2 - __half2float(h2), l3 = x3 - __half2float(h3);
            int wsw = w ^ swz;
            int off = kc16 * 1024 + row * 8 + wsw;
            *(uint2*)(smf + W_AH + off) =
                make_uint2(pkh(__half2float(h0), __half2float(h1)),
                           pkh(__half2float(h2), __half2float(h3)));
            *(uint2*)(smf + W_AL + off) = make_uint2(pkh(l0, l1), pkh(l2, l3));
        }
    }
    load_b_tile(smem_base, 0, tid); CP_COMMIT();
    load_b_tile(smem_base, 1, tid); CP_COMMIT();

    float best[4];
    int bcol[4];
#pragma unroll
    for (int s = 0; s < 4; s++) { best[s] = -3.4e38f; bcol[s] = 0; }

    const uint32_t* AH = (const uint32_t*)(smf + W_AH);
    const uint32_t* ALp = (const uint32_t*)(smf + W_AL);
    const int aswz = ((g >> 2) & 1) << 2;
    const int w0 = kl ^ aswz, w1 = (kl + 4) ^ aswz;

    for (int t = 0; t < NTILES; t++) {
        CP_WAIT1();
        __syncthreads();
        const uint32_t* BH = (const uint32_t*)(smf + W_B + (t & 1) * 8192);
        const uint32_t* BL = BH + 4096;
        const float* cn = smf + W_CN + (t & 1) * 128 + wc * 64;

        float acc[2][8][4];
#pragma unroll
        for (int nf = 0; nf < 8; nf++) {
            float c0 = cn[nf * 8 + 2 * kl];
            float c1 = cn[nf * 8 + 2 * kl + 1];
#pragma unroll
            for (int m = 0; m < 2; m++) {
                acc[m][nf][0] = c0; acc[m][nf][1] = c1;
                acc[m][nf][2] = c0; acc[m][nf][3] = c1;
            }
        }
#pragma unroll
        for (int kc16 = 0; kc16 < 4; kc16++) {
            uint32_t ah[2][4], al[2][4];
#pragma unroll
            for (int m = 0; m < 2; m++) {
                int base = kc16 * 1024 + (wr * 32 + m * 16 + g) * 8;
                ah[m][0] = AH[base + w0];      ah[m][1] = AH[base + 64 + w0];
                ah[m][2] = AH[base + w1];      ah[m][3] = AH[base + 64 + w1];
                al[m][0] = ALp[base + w0];     al[m][1] = ALp[base + 64 + w0];
                al[m][2] = ALp[base + w1];     al[m][3] = ALp[base + 64 + w1];
            }
#pragma unroll
            for (int nf = 0; nf < 8; nf++) {
                int bb = kc16 * 1024 + (wc * 64 + nf * 8 + g) * 8;
                uint32_t bh0 = BH[bb + w0], bh1 = BH[bb + w1];
                uint32_t bl0 = BL[bb + w0], bl1 = BL[bb + w1];
                mma16(acc[0][nf], ah[0], bh0, bh1);
                mma16(acc[0][nf], ah[0], bl0, bl1);
                mma16(acc[0][nf], al[0], bh0, bh1);
                mma16(acc[1][nf], ah[1], bh0, bh1);
                mma16(acc[1][nf], ah[1], bl0, bl1);
                mma16(acc[1][nf], al[1], bh0, bh1);
            }
        }
        // running per-slot argmax (ascending cols -> strict > keeps low index)
        int colbase0 = t * 128 + wc * 64 + 2 * kl;
#pragma unroll
        for (int m = 0; m < 2; m++) {
#pragma unroll
            for (int nf = 0; nf < 8; nf++) {
                int c01 = colbase0 + nf * 8;
                float v0 = acc[m][nf][0], v1 = acc[m][nf][1];
                float v2 = acc[m][nf][2], v3 = acc[m][nf][3];
                int s0 = 2 * m, s1 = 2 * m + 1;
                if (v0 > best[s0]) { best[s0] = v0; bcol[s0] = c01; }
                if (v1 > best[s0]) { best[s0] = v1; bcol[s0] = c01 + 1; }
                if (v2 > best[s1]) { best[s1] = v2; bcol[s1] = c01; }
                if (v3 > best[s1]) { best[s1] = v3; bcol[s1] = c01 + 1; }
            }
        }
        __syncthreads();
        if (t + 2 < NTILES) load_b_tile(smem_base, t + 2, tid);
        CP_COMMIT();
    }

    // ---- quad reduce ----
#pragma unroll
    for (int s = 0; s < 4; s++) {
        float v = best[s];
        int c = bcol[s];
#pragma unroll
        for (int off = 1; off <= 2; off <<= 1) {
            float ov = __shfl_xor_sync(0xffffffffu, v, off);
            int oc = __shfl_xor_sync(0xffffffffu, c, off);
            if (ov > v || (ov == v && oc < c)) { v = ov; c = oc; }
        }
        if ((lane & 3) == 0) {
            int rowl = wr * 32 + (s >> 1) * 16 + (s & 1) * 8 + g;
            RED[wc * 128 + rowl] = make_float2(v, __int_as_float(c));
        }
    }
    __syncthreads();

    // ---- exact fp32 rescore of the two half-winners per row ----
    if (tid < 128) {
        int row = tid, rg = row0 + row;
        float xv[64];
        const float4* ip = (const float4*)(input + (size_t)rg * 64);
        const float4* pp = (const float4*)(g_pe + (size_t)(rg & 1023) * 64);
#pragma unroll
        for (int q = 0; q < 16; q++) {
            float4 a = ip[q], b = pp[q];
            xv[q * 4 + 0] = a.x + b.x; xv[q * 4 + 1] = a.y + b.y;
            xv[q * 4 + 2] = a.z + b.z; xv[q * 4 + 3] = a.w + b.w;
        }
        int c0 = __float_as_int(RED[row].y);
        int c1 = __float_as_int(RED[128 + row].y);
        float s0 = g_cn[c0], s1 = g_cn[c1];
        const float4* e0 = (const float4*)(g_et + (size_t)c0 * 64);
        const float4* e1 = (const float4*)(g_et + (size_t)c1 * 64);
#pragma unroll
        for (int q = 0; q < 16; q++) {
            float4 ea = e0[q], eb = e1[q];
            s0 = fmaf(xv[q * 4 + 0], ea.x, s0); s0 = fmaf(xv[q * 4 + 1], ea.y, s0);
            s0 = fmaf(xv[q * 4 + 2], ea.z, s0); s0 = fmaf(xv[q * 4 + 3], ea.w, s0);
            s1 = fmaf(xv[q * 4 + 0], eb.x, s1); s1 = fmaf(xv[q * 4 + 1], eb.y, s1);
            s1 = fmaf(xv[q * 4 + 2], eb.z, s1); s1 = fmaf(xv[q * 4 + 3], eb.w, s1);
        }
        int bj = (s1 > s0 || (s1 == s0 && c1 < c0)) ? c1 : c0;
        IndSh[row] = bj;
        if (full) out[OFF_IND + rg] = (float)bj;
        atomicAdd(&g_counts[bj], 1.0f);
    }
    __syncthreads();

    // ---- epilogue: quantize gather, loss, embed_sum scatter ----
    {
        float lsum = 0.0f;
        for (int it = 0; it < 16; it++) {
            int rloc = wid * 16 + it;
            int rg = row0 + rloc;
            int j = IndSh[rloc];
#pragma unroll
            for (int h2 = 0; h2 < 2; h2++) {
                int k = lane + 32 * h2;
                float ev = g_et[(size_t)j * 64 + k];
                float iv = input[(size_t)rg * 64 + k];
                float dd = ev - iv;
                lsum += dd * dd;
                out[OFF_Q + (size_t)rg * 64 + k] = ev;
                float xv2 = iv + g_pe[(rg & 1023) * 64 + k];
                atomicAdd(&g_esum[(size_t)k * NCODES + j], xv2);
            }
        }
#pragma unroll
        for (int off = 16; off; off >>= 1)
            lsum += __shfl_down_sync(0xffffffffu, lsum, off);
        if (lane == 0) atomicAdd(smf + W_LOSS, lsum);
    }
    __syncthreads();
    if (tid == 0) atomicAdd(&g_loss, smf[W_LOSS]);
}

// ---------------------------------------------------------------------------
__global__ void vq_fin1(const float* __restrict__ cs, float* __restrict__ out) {
    int j = blockIdx.x * 256 + threadIdx.x;
    float nc = 0.8f * cs[j] + 0.2f * g_counts[j];
    out[OFF_NC + j] = nc;
    __shared__ float sh[256];
    sh[threadIdx.x] = nc;
    __syncthreads();
    for (int s = 128; s; s >>= 1) {
        if (threadIdx.x < s) sh[threadIdx.x] += sh[threadIdx.x + s];
        __syncthreads();
    }
    if (threadIdx.x == 0) atomicAdd(&g_total, sh[0]);
}

__global__ void vq_fin2(const float* __restrict__ ea, float* __restrict__ out) {
    int idx = blockIdx.x * 256 + threadIdx.x;
    int j = idx & (NCODES - 1);
    float nea = 0.8f * ea[idx] + 0.2f * g_esum[idx];
    out[OFF_EA + idx] = nea;
    float total = g_total;
    float nc = out[OFF_NC + j];
    float smoothed = (nc + 1e-5f) / (total + NCODES * 1e-5f) * total;
    out[OFF_NE + idx] = nea / smoothed;
    if (idx == 0) out[OFF_LOSS] = g_loss * (1.0f / 2097152.0f);
}

// ---------------------------------------------------------------------------
extern "C" void kernel_launch(void* const* d_in, const int* in_sizes, int n_in,
                              void* d_out, int out_size) {
    const float* input = (const float*)d_in[0];
    const float* embed = (const float*)d_in[1];
    const float* pos   = (const float*)d_in[2];
    const float* cs    = (const float*)d_in[3];
    const float* ea    = (const float*)d_in[4];
    float* out = (float*)d_out;

    cudaFuncSetAttribute(vq_main, cudaFuncAttributeMaxDynamicSharedMemorySize,
                         SMEM_TOTAL);
    int full = (out_size >= OUT_FULL) ? 1 : 0;

    vq_prep0<<<2048, 256>>>(pos);
    vq_prep1<<<64, 256>>>(embed);
    vq_main<<<256, 256, SMEM_TOTAL>>>(input, out, full);
    if (full) {
        vq_fin1<<<NCODES / 256, 256>>>(cs, out);
        vq_fin2<<<(64 * NCODES) / 256, 256>>>(ea, out);
    }
}